// round 8
// baseline (speedup 1.0000x reference)
#include <cuda_runtime.h>

// SiluAndMul: x [M, 2N] fp32 -> out [M, N] fp32, out = silu(x[:, :N]) * x[:, N:]
// M = 16384, N = 11008. Pure HBM-bound: 2.164 GB/launch, ~7.15 TB/s measured
// controller ceiling -> ~299.7us floor.
// R8 probe: persistent exact-fill grid. 592 CTAs (148 SM x 4 CTA x 256 thr,
// regs=24 -> exactly 32 warps/SM, occ ~100%) grid-striding the flat float4
// index space. Removes ~400 scheduling waves + 179k CTA starts; raises warp
// count for latency hiding. Same coalesced sequential sweep; plain
// evict-normal ld/st (streaming hints measured slower in R2-R4).

static constexpr int M = 16384;
static constexpr int N = 11008;               // output cols
static constexpr int N4 = N / 4;              // 2752 float4 per output row
static constexpr int TWO_N4 = 2 * N4;         // input row stride in float4
static constexpr long long TOTAL4 = (long long)M * N4;  // 45,088,768
static constexpr int BLOCK = 256;
static constexpr int GRID = 148 * 4;          // 592 CTAs = exact chip fill

__global__ __launch_bounds__(BLOCK) void silu_and_mul_kernel(
    const float* __restrict__ x, float* __restrict__ out)
{
    const float4* __restrict__ x4 = reinterpret_cast<const float4*>(x);
    float4* __restrict__ out4     = reinterpret_cast<float4*>(out);

    const long long stride = (long long)GRID * BLOCK;   // 151,552

    for (long long idx = (long long)blockIdx.x * BLOCK + threadIdx.x;
         idx < TOTAL4; idx += stride)
    {
        // row = idx / N4, col = idx % N4 (N4 = 2752 = 2^6 * 43: one mulhi div)
        const long long row = idx / N4;
        const int col4 = (int)(idx - row * N4);
        const long long in_base = row * TWO_N4;

        float4 g = x4[in_base + col4];
        float4 u = x4[in_base + N4 + col4];

        float4 r;
        r.x = (g.x * __frcp_rn(1.0f + __expf(-g.x))) * u.x;
        r.y = (g.y * __frcp_rn(1.0f + __expf(-g.y))) * u.y;
        r.z = (g.z * __frcp_rn(1.0f + __expf(-g.z))) * u.z;
        r.w = (g.w * __frcp_rn(1.0f + __expf(-g.w))) * u.w;

        out4[idx] = r;
    }
}

extern "C" void kernel_launch(void* const* d_in, const int* in_sizes, int n_in,
                              void* d_out, int out_size)
{
    const float* x = (const float*)d_in[0];
    float* out = (float*)d_out;

    silu_and_mul_kernel<<<GRID, BLOCK>>>(x, out);
}

// round 9
// speedup vs baseline: 1.2028x; 1.2028x over previous
#include <cuda_runtime.h>

// SiluAndMul: x [M, 2N] fp32 -> out [M, N] fp32, out = silu(x[:, :N]) * x[:, N:]
// M = 16384, N = 11008. Pure HBM-bound: 2.164 GB/launch.
//
// FINAL kernel — converged after 8-round sweep on GB300 (sm_103a):
//   R1/R5/R7 (this config):          299.5us, DRAM 90%, 7.16 TB/s
//   R2/R3 __ldcs/__stcs + unroll:    303.8us (streaming hints add bus turnarounds)
//   R4 __stcs only:                  301.3us
//   R6 1D exact-cover grid:          301.1us (64-bit div overhead, no benefit)
//   R8 persistent 592-CTA grid:      360.6us (loop-carried MLP collapse, DRAM 76%)
//
// Governing mechanism: bandwidth here = outstanding-load parallelism. The
// 180k-CTA one-shot launch keeps the DRAM queues maximally full; every
// "optimization" that reduced independent in-flight loads lost bandwidth.
// 299.5us timed = 99.9% of the 2.164GB / 7.15TB/s analytic floor (299.7us);
// the residual ~10% to 8 TB/s spec is refresh + R/W turnaround, not
// kernel-addressable for a 2:1 read:write stream.

static constexpr int M = 16384;
static constexpr int N = 11008;         // output cols
static constexpr int TWO_N = 2 * N;     // input row stride (floats)
static constexpr int N4 = N / 4;        // 2752 float4 per output row

__global__ __launch_bounds__(256) void silu_and_mul_kernel(
    const float* __restrict__ x, float* __restrict__ out)
{
    const int col4 = blockIdx.x * blockDim.x + threadIdx.x;  // float4 column index
    if (col4 >= N4) return;
    const long long row = blockIdx.y;

    const float4* gate4 = reinterpret_cast<const float4*>(x + row * TWO_N);
    const float4* up4   = reinterpret_cast<const float4*>(x + row * TWO_N + N);
    float4* out4        = reinterpret_cast<float4*>(out + row * (long long)N);

    float4 g = gate4[col4];
    float4 u = up4[col4];

    float4 r;
    r.x = (g.x * __frcp_rn(1.0f + __expf(-g.x))) * u.x;
    r.y = (g.y * __frcp_rn(1.0f + __expf(-g.y))) * u.y;
    r.z = (g.z * __frcp_rn(1.0f + __expf(-g.z))) * u.z;
    r.w = (g.w * __frcp_rn(1.0f + __expf(-g.w))) * u.w;

    out4[col4] = r;
}

extern "C" void kernel_launch(void* const* d_in, const int* in_sizes, int n_in,
                              void* d_out, int out_size)
{
    const float* x = (const float*)d_in[0];
    float* out = (float*)d_out;

    dim3 block(256);
    dim3 grid((N4 + 255) / 256, M);   // (11, 16384)
    silu_and_mul_kernel<<<grid, block>>>(x, out);
}